// round 9
// baseline (speedup 1.0000x reference)
#include <cuda_runtime.h>
#include <cuda_fp16.h>
#include <cstdint>

#define BATCH 8
#define LQ 2048
#define LY 2048
#define DIM 64
#define EPSN 1e-8f

#define RS 72                    // operand tile row stride in halves (144 B)
#define TILE_HB (128 * RS * 2)   // 18432 B per operand tile
#define SM_TOTAL (3 * TILE_HB)   // A + 2 B tiles = 55296 B dynamic smem

// fp16 normalized operands (validated error ~2.9e-4 rel vs 1e-3 gate)
__device__ __half g_q[(size_t)BATCH * LQ * DIM];
__device__ __half g_y[(size_t)BATCH * LY * DIM];

__device__ __forceinline__ uint32_t smem_u32(const void* p) {
    uint32_t a;
    asm("{ .reg .u64 t; cvta.to.shared.u64 t, %1; cvt.u32.u64 %0, t; }"
        : "=r"(a) : "l"(p));
    return a;
}
__device__ __forceinline__ void atomicMaxFloat(float* addr, float v) {
    if (v >= 0.0f)
        atomicMax((int*)addr, __float_as_int(v));
    else
        atomicMin((unsigned int*)addr, __float_as_uint(v));
}

#define LDSM_X4(r0, r1, r2, r3, addr)                                          \
    asm volatile("ldmatrix.sync.aligned.m8n8.x4.shared.b16 {%0,%1,%2,%3}, [%4];" \
                 : "=r"(r0), "=r"(r1), "=r"(r2), "=r"(r3) : "r"(addr))

#define MMA_F16(d, a, bf)                                                      \
    asm volatile(                                                              \
        "mma.sync.aligned.m16n8k16.row.col.f32.f16.f16.f32 "                  \
        "{%0,%1,%2,%3}, {%4,%5,%6,%7}, {%8,%9}, {%0,%1,%2,%3};"               \
        : "+f"(d[0]), "+f"(d[1]), "+f"(d[2]), "+f"(d[3])                       \
        : "r"(a[0]), "r"(a[1]), "r"(a[2]), "r"(a[3]), "r"(bf[0]), "r"(bf[1]))

#define CP_ASYNC_CG16(smaddr, gptr)                                            \
    asm volatile("cp.async.cg.shared.global [%0], [%1], 16;"                    \
                 :: "r"(smaddr), "l"(gptr))

// ---------------------------------------------------------------------------
// Prep: normalize -> fp16. 4 rows per warp. Also inits sim on q rows.
// ---------------------------------------------------------------------------
__global__ void prep_kernel(const float* __restrict__ q,
                            const float* __restrict__ y,
                            float* __restrict__ sim) {
    int gw   = (blockIdx.x * blockDim.x + threadIdx.x) >> 5;
    int lane = threadIdx.x & 31;
    int r    = gw * 4 + (lane >> 3);
    int j    = lane & 7;
    const int rows = BATCH * LQ;
    if (r >= 2 * rows) return;
    bool isQ = r < rows;
    int row  = isQ ? r : r - rows;

    const float4* src = (const float4*)((isQ ? q : y) + (size_t)row * DIM);
    float4 v1 = src[j * 2];
    float4 v2 = src[j * 2 + 1];
    float ss = v1.x * v1.x + v1.y * v1.y + v1.z * v1.z + v1.w * v1.w +
               v2.x * v2.x + v2.y * v2.y + v2.z * v2.z + v2.w * v2.w;
    ss += __shfl_xor_sync(0xffffffffu, ss, 1);
    ss += __shfl_xor_sync(0xffffffffu, ss, 2);
    ss += __shfl_xor_sync(0xffffffffu, ss, 4);
    float inv = 1.0f / fmaxf(sqrtf(ss), EPSN);

    __half2 h[4];
    h[0] = __floats2half2_rn(v1.x * inv, v1.y * inv);
    h[1] = __floats2half2_rn(v1.z * inv, v1.w * inv);
    h[2] = __floats2half2_rn(v2.x * inv, v2.y * inv);
    h[3] = __floats2half2_rn(v2.z * inv, v2.w * inv);
    __half* dst = (isQ ? g_q : g_y) + (size_t)row * DIM + j * 8;
    *(uint4*)dst = *(uint4*)h;
    if (isQ && j == 0) sim[row] = __int_as_float(0xff800000);
}

// ---------------------------------------------------------------------------
// HMMA GEMM: CTA = 128(q) x 256(y) supertile, 8 warps (4x2), warp 32x64/tile.
// Epilogue: shfl-paired register transpose -> STG.128 (no smem staging).
// ---------------------------------------------------------------------------
__global__ __launch_bounds__(256, 2)
void gemm_kernel(float* __restrict__ att, float* __restrict__ sim) {
    extern __shared__ char smem[];
    const uint32_t smA = smem_u32(smem);
    const uint32_t smB = smA + TILE_HB;

    const int tid  = threadIdx.x;
    const int lane = tid & 31;
    const int wid  = tid >> 5;
    const int wm   = wid & 3;    // q group (32 rows)
    const int wn   = wid >> 2;   // y group (64 cols)

    const int b   = blockIdx.z;
    const int yt0 = blockIdx.x * 256;
    const int qt  = blockIdx.y * 128;

    // --- async fills: A (1024 float4) + B0|B1 (2048 float4) ---
    const float4* qsrc = (const float4*)(g_q + ((size_t)b * LQ + qt) * DIM);
    const float4* ysrc = (const float4*)(g_y + ((size_t)b * LY + yt0) * DIM);
#pragma unroll
    for (int it = 0; it < 4; it++) {
        int idx = it * 256 + tid;
        int row = idx >> 3, c = idx & 7;
        CP_ASYNC_CG16(smA + row * (RS * 2) + c * 16, qsrc + idx);
    }
#pragma unroll
    for (int it = 0; it < 8; it++) {
        int idx = it * 256 + tid;
        int row = idx >> 3, c = idx & 7;
        CP_ASYNC_CG16(smB + row * (RS * 2) + c * 16, ysrc + idx);
    }
    asm volatile("cp.async.commit_group;" ::: "memory");

    uint32_t aaddr[2];
#pragma unroll
    for (int mi = 0; mi < 2; mi++) {
        int row = wm * 32 + mi * 16 + (lane & 15);
        aaddr[mi] = smA + row * (RS * 2) + ((lane >> 4) & 1) * 16;
    }
    uint32_t baddr[4];
#pragma unroll
    for (int np = 0; np < 4; np++) {
        int n = wn * 64 + np * 16 + (lane & 7) + ((lane >> 4) & 1) * 8;
        baddr[np] = smB + n * (RS * 2) + ((lane >> 3) & 1) * 16;
    }

    asm volatile("cp.async.wait_group 0;" ::: "memory");
    __syncthreads();

    const int qlane = lane >> 2;       // c-frag row within 8-row group
    const int npair = lane & 3;        // c-frag column pair
    const int plane = npair & 1;       // pair member (partner = lane^1)
    const int phi   = npair >> 1;      // which 4-col half of the 8-col group

#pragma unroll
    for (int t = 0; t < 2; t++) {
        const uint32_t bB = t * TILE_HB;
        float acc[2][8][4];
#pragma unroll
        for (int mi = 0; mi < 2; mi++)
#pragma unroll
            for (int ni = 0; ni < 8; ni++)
#pragma unroll
                for (int e = 0; e < 4; e++) acc[mi][ni][e] = 0.0f;

#pragma unroll
        for (int ks = 0; ks < 4; ks++) {
            uint32_t bf[8][2];
#pragma unroll
            for (int np = 0; np < 4; np++)
                LDSM_X4(bf[2 * np][0], bf[2 * np][1], bf[2 * np + 1][0],
                        bf[2 * np + 1][1], baddr[np] + bB + ks * 32);
            uint32_t a[2][4];
#pragma unroll
            for (int mi = 0; mi < 2; mi++)
                LDSM_X4(a[mi][0], a[mi][1], a[mi][2], a[mi][3],
                        aaddr[mi] + ks * 32);
#pragma unroll
            for (int mi = 0; mi < 2; mi++)
#pragma unroll
                for (int ni = 0; ni < 8; ni++)
                    MMA_F16(acc[mi][ni], a[mi], bf[ni]);
        }

        // --- Epilogue: shfl-paired transpose -> STG.128, fused row-max ---
        const int yt = yt0 + t * 128;
#pragma unroll
        for (int mi = 0; mi < 2; mi++) {
#pragma unroll
            for (int h = 0; h < 2; h++) {
                int qrow = qt + wm * 32 + mi * 16 + h * 8 + qlane;
                float* outrow =
                    att + ((size_t)b * LQ + qrow) * LY + yt + wn * 64;

                float m = __int_as_float(0xff800000);
#pragma unroll
                for (int ni = 0; ni < 8; ni++)
                    m = fmaxf(m, fmaxf(acc[mi][ni][2 * h],
                                       acc[mi][ni][2 * h + 1]));
                m = fmaxf(m, __shfl_xor_sync(0xffffffffu, m, 1));
                m = fmaxf(m, __shfl_xor_sync(0xffffffffu, m, 2));
                if (npair == 0)
                    atomicMaxFloat(&sim[(size_t)b * LQ + qrow], m);

#pragma unroll
                for (int k = 0; k < 4; k++) {
                    int nt = 2 * k + plane;        // my target ni
                    int ns = 2 * k + 1 - plane;    // partner's target ni
                    float sx = acc[mi][ns][2 * h];
                    float sy = acc[mi][ns][2 * h + 1];
                    float rx = __shfl_xor_sync(0xffffffffu, sx, 1);
                    float ry = __shfl_xor_sync(0xffffffffu, sy, 1);
                    float ox = acc[mi][nt][2 * h];
                    float oy = acc[mi][nt][2 * h + 1];
                    float4 v = plane ? make_float4(rx, ry, ox, oy)
                                     : make_float4(ox, oy, rx, ry);
                    int col = 8 * nt + 4 * phi;    // = 16k + 8*plane + 4*phi
                    __stcs((float4*)(outrow + col), v);
                }
            }
        }
    }
}

// ---------------------------------------------------------------------------
extern "C" void kernel_launch(void* const* d_in, const int* in_sizes, int n_in,
                              void* d_out, int out_size) {
    const float* q = (const float*)d_in[0];
    const float* y = (const float*)d_in[1];
    float* att = (float*)d_out;
    float* sim = att + (size_t)BATCH * LQ * LY;

    static bool attr_done = false;
    if (!attr_done) {
        cudaFuncSetAttribute(gemm_kernel,
                             cudaFuncAttributeMaxDynamicSharedMemorySize,
                             SM_TOTAL);
        attr_done = true;
    }

    int warps = (2 * BATCH * LQ) / 4;
    prep_kernel<<<(warps * 32 + 255) / 256, 256>>>(q, y, sim);

    dim3 grid(LY / 256, LQ / 128, BATCH);
    gemm_kernel<<<grid, 256, SM_TOTAL>>>(att, sim);
}

// round 10
// speedup vs baseline: 1.5455x; 1.5455x over previous
#include <cuda_runtime.h>
#include <cuda_fp16.h>
#include <cstdint>

#define BATCH 8
#define LQ 2048
#define LY 2048
#define DIM 64
#define EPSN 1e-8f

#define RS 72                    // operand tile row stride in halves (144 B)
#define TILE_HB (128 * RS * 2)   // 18432 B per operand tile
#define SM_TOTAL (3 * TILE_HB)   // A + 2 B tiles = 55296 B dynamic smem

// fp16 normalized operands (validated error ~2.9e-4 rel vs 1e-3 gate)
__device__ __half g_q[(size_t)BATCH * LQ * DIM];
__device__ __half g_y[(size_t)BATCH * LY * DIM];

__device__ __forceinline__ uint32_t smem_u32(const void* p) {
    uint32_t a;
    asm("{ .reg .u64 t; cvta.to.shared.u64 t, %1; cvt.u32.u64 %0, t; }"
        : "=r"(a) : "l"(p));
    return a;
}
__device__ __forceinline__ void atomicMaxFloat(float* addr, float v) {
    if (v >= 0.0f)
        atomicMax((int*)addr, __float_as_int(v));
    else
        atomicMin((unsigned int*)addr, __float_as_uint(v));
}

#define LDSM_X4(r0, r1, r2, r3, addr)                                          \
    asm volatile("ldmatrix.sync.aligned.m8n8.x4.shared.b16 {%0,%1,%2,%3}, [%4];" \
                 : "=r"(r0), "=r"(r1), "=r"(r2), "=r"(r3) : "r"(addr))

#define MMA_F16(d, a, bf)                                                      \
    asm volatile(                                                              \
        "mma.sync.aligned.m16n8k16.row.col.f32.f16.f16.f32 "                  \
        "{%0,%1,%2,%3}, {%4,%5,%6,%7}, {%8,%9}, {%0,%1,%2,%3};"               \
        : "+f"(d[0]), "+f"(d[1]), "+f"(d[2]), "+f"(d[3])                       \
        : "r"(a[0]), "r"(a[1]), "r"(a[2]), "r"(a[3]), "r"(bf[0]), "r"(bf[1]))

#define CP_ASYNC_CG16(smaddr, gptr)                                            \
    asm volatile("cp.async.cg.shared.global [%0], [%1], 16;"                    \
                 :: "r"(smaddr), "l"(gptr))

// ---------------------------------------------------------------------------
// Prep: normalize -> fp16. 4 rows per warp. Also inits sim on q rows.
// ---------------------------------------------------------------------------
__global__ void prep_kernel(const float* __restrict__ q,
                            const float* __restrict__ y,
                            float* __restrict__ sim) {
    int gw   = (blockIdx.x * blockDim.x + threadIdx.x) >> 5;
    int lane = threadIdx.x & 31;
    int r    = gw * 4 + (lane >> 3);
    int j    = lane & 7;
    const int rows = BATCH * LQ;
    if (r >= 2 * rows) return;
    bool isQ = r < rows;
    int row  = isQ ? r : r - rows;

    const float4* src = (const float4*)((isQ ? q : y) + (size_t)row * DIM);
    float4 v1 = src[j * 2];
    float4 v2 = src[j * 2 + 1];
    float ss = v1.x * v1.x + v1.y * v1.y + v1.z * v1.z + v1.w * v1.w +
               v2.x * v2.x + v2.y * v2.y + v2.z * v2.z + v2.w * v2.w;
    ss += __shfl_xor_sync(0xffffffffu, ss, 1);
    ss += __shfl_xor_sync(0xffffffffu, ss, 2);
    ss += __shfl_xor_sync(0xffffffffu, ss, 4);
    float inv = 1.0f / fmaxf(sqrtf(ss), EPSN);

    __half2 h[4];
    h[0] = __floats2half2_rn(v1.x * inv, v1.y * inv);
    h[1] = __floats2half2_rn(v1.z * inv, v1.w * inv);
    h[2] = __floats2half2_rn(v2.x * inv, v2.y * inv);
    h[3] = __floats2half2_rn(v2.z * inv, v2.w * inv);
    __half* dst = (isQ ? g_q : g_y) + (size_t)row * DIM + j * 8;
    *(uint4*)dst = *(uint4*)h;
    if (isQ && j == 0) sim[row] = __int_as_float(0xff800000);
}

// ---------------------------------------------------------------------------
// HMMA GEMM: CTA = 128(q) x 256(y) supertile, 8 warps (4x2), warp 32x64/tile.
// Epilogue: xor1 shfl transpose (static acc indices!) -> STG.128.
// ---------------------------------------------------------------------------
__global__ __launch_bounds__(256, 2)
void gemm_kernel(float* __restrict__ att, float* __restrict__ sim) {
    extern __shared__ char smem[];
    const uint32_t smA = smem_u32(smem);
    const uint32_t smB = smA + TILE_HB;

    const int tid  = threadIdx.x;
    const int lane = tid & 31;
    const int wid  = tid >> 5;
    const int wm   = wid & 3;    // q group (32 rows)
    const int wn   = wid >> 2;   // y group (64 cols)

    const int b   = blockIdx.z;
    const int yt0 = blockIdx.x * 256;
    const int qt  = blockIdx.y * 128;

    // --- async fills: A (1024 float4) + B0|B1 (2048 float4) ---
    const float4* qsrc = (const float4*)(g_q + ((size_t)b * LQ + qt) * DIM);
    const float4* ysrc = (const float4*)(g_y + ((size_t)b * LY + yt0) * DIM);
#pragma unroll
    for (int it = 0; it < 4; it++) {
        int idx = it * 256 + tid;
        int row = idx >> 3, c = idx & 7;
        CP_ASYNC_CG16(smA + row * (RS * 2) + c * 16, qsrc + idx);
    }
#pragma unroll
    for (int it = 0; it < 8; it++) {
        int idx = it * 256 + tid;
        int row = idx >> 3, c = idx & 7;
        CP_ASYNC_CG16(smB + row * (RS * 2) + c * 16, ysrc + idx);
    }
    asm volatile("cp.async.commit_group;" ::: "memory");

    uint32_t aaddr[2];
#pragma unroll
    for (int mi = 0; mi < 2; mi++) {
        int row = wm * 32 + mi * 16 + (lane & 15);
        aaddr[mi] = smA + row * (RS * 2) + ((lane >> 4) & 1) * 16;
    }
    uint32_t baddr[4];
#pragma unroll
    for (int np = 0; np < 4; np++) {
        int n = wn * 64 + np * 16 + (lane & 7) + ((lane >> 4) & 1) * 8;
        baddr[np] = smB + n * (RS * 2) + ((lane >> 3) & 1) * 16;
    }

    asm volatile("cp.async.wait_group 0;" ::: "memory");
    __syncthreads();

    const int qlane = lane >> 2;       // c-frag row within 8-row group
    const int npair = lane & 3;        // c-frag column pair
    const bool pl   = npair & 1;       // pair member (partner = lane^1)
    const int phi   = npair >> 1;      // 4-col half within 16-col k group

#pragma unroll
    for (int t = 0; t < 2; t++) {
        const uint32_t bB = t * TILE_HB;
        float acc[2][8][4];
#pragma unroll
        for (int mi = 0; mi < 2; mi++)
#pragma unroll
            for (int ni = 0; ni < 8; ni++)
#pragma unroll
                for (int e = 0; e < 4; e++) acc[mi][ni][e] = 0.0f;

#pragma unroll
        for (int ks = 0; ks < 4; ks++) {
            uint32_t bf[8][2];
#pragma unroll
            for (int np = 0; np < 4; np++)
                LDSM_X4(bf[2 * np][0], bf[2 * np][1], bf[2 * np + 1][0],
                        bf[2 * np + 1][1], baddr[np] + bB + ks * 32);
            uint32_t a[2][4];
#pragma unroll
            for (int mi = 0; mi < 2; mi++)
                LDSM_X4(a[mi][0], a[mi][1], a[mi][2], a[mi][3],
                        aaddr[mi] + ks * 32);
#pragma unroll
            for (int mi = 0; mi < 2; mi++)
#pragma unroll
                for (int ni = 0; ni < 8; ni++)
                    MMA_F16(acc[mi][ni], a[mi], bf[ni]);
        }

        // --- Epilogue: xor1 shfl transpose, all acc indices compile-time ---
        const int yt = yt0 + t * 128;
#pragma unroll
        for (int mi = 0; mi < 2; mi++) {
#pragma unroll
            for (int h = 0; h < 2; h++) {
                int qrow = qt + wm * 32 + mi * 16 + h * 8 + qlane;
                float* outrow =
                    att + ((size_t)b * LQ + qrow) * LY + yt + wn * 64;

                float m = __int_as_float(0xff800000);
#pragma unroll
                for (int ni = 0; ni < 8; ni++)
                    m = fmaxf(m, fmaxf(acc[mi][ni][2 * h],
                                       acc[mi][ni][2 * h + 1]));
                m = fmaxf(m, __shfl_xor_sync(0xffffffffu, m, 1));
                m = fmaxf(m, __shfl_xor_sync(0xffffffffu, m, 2));
                if (npair == 0)
                    atomicMaxFloat(&sim[(size_t)b * LQ + qrow], m);

#pragma unroll
                for (int k = 0; k < 4; k++) {
                    // static indices: even/odd column-pair accs for this k
                    float ax = acc[mi][2 * k][2 * h];
                    float ay = acc[mi][2 * k][2 * h + 1];
                    float bx = acc[mi][2 * k + 1][2 * h];
                    float by = acc[mi][2 * k + 1][2 * h + 1];
                    // give partner the pair it needs (SELs, no array index)
                    float2 give = make_float2(pl ? ax : bx, pl ? ay : by);
                    long long gp;
                    memcpy(&gp, &give, 8);
                    long long rp = __shfl_xor_sync(0xffffffffu, gp, 1);
                    float2 rec;
                    memcpy(&rec, &rp, 8);
                    float4 v = pl ? make_float4(rec.x, rec.y, bx, by)
                                  : make_float4(ax, ay, rec.x, rec.y);
                    // col = 16k + 8*pl + 4*phi
                    __stcs((float4*)(outrow + 16 * k + (pl ? 8 : 0) + 4 * phi),
                           v);
                }
            }
        }
    }
}

// ---------------------------------------------------------------------------
extern "C" void kernel_launch(void* const* d_in, const int* in_sizes, int n_in,
                              void* d_out, int out_size) {
    const float* q = (const float*)d_in[0];
    const float* y = (const float*)d_in[1];
    float* att = (float*)d_out;
    float* sim = att + (size_t)BATCH * LQ * LY;

    static bool attr_done = false;
    if (!attr_done) {
        cudaFuncSetAttribute(gemm_kernel,
                             cudaFuncAttributeMaxDynamicSharedMemorySize,
                             SM_TOTAL);
        attr_done = true;
    }

    int warps = (2 * BATCH * LQ) / 4;
    prep_kernel<<<(warps * 32 + 255) / 256, 256>>>(q, y, sim);

    dim3 grid(LY / 256, LQ / 128, BATCH);
    gemm_kernel<<<grid, 256, SM_TOTAL>>>(att, sim);
}